// round 8
// baseline (speedup 1.0000x reference)
#include <cuda_runtime.h>

#define BN 8
#define SN 2048
#define EN 8
#define NTOK (BN*SN)
#define KSPLIT 16
#define KCHUNK (SN/KSPLIT)   /* 128 keys per split == one smem tile */
#define TK 128               /* keys per smem tile (64 key-pairs) */
#define NTHR 128             /* threads per CTA; each thread owns 2 queries */
#define QPC 256              /* queries per CTA */
#define NQT (SN/QPC)         /* 8 query tiles */
#define LOG2E 1.4426950408889634f

typedef unsigned long long u64;

/* Scratch (allocation-free rule: device globals) */
__device__ float g_den[(size_t)NTOK * KSPLIT];
__device__ float g_num[(size_t)NTOK * KSPLIT * 8];
__device__ unsigned int g_cnt[BN * NQT];   /* zero-init; each run returns it to 0 */

/* ---- packed f32x2 helpers (Blackwell FFMA2 via PTX) ---- */
__device__ __forceinline__ u64 fma2(u64 a, u64 b, u64 c) {
    u64 d;
    asm("fma.rn.f32x2 %0, %1, %2, %3;" : "=l"(d) : "l"(a), "l"(b), "l"(c));
    return d;
}
__device__ __forceinline__ u64 mul2(u64 a, u64 b) {
    u64 d;
    asm("mul.rn.f32x2 %0, %1, %2;" : "=l"(d) : "l"(a), "l"(b));
    return d;
}
__device__ __forceinline__ u64 add2(u64 a, u64 b) {
    u64 d;
    asm("add.rn.f32x2 %0, %1, %2;" : "=l"(d) : "l"(a), "l"(b));
    return d;
}
__device__ __forceinline__ float2 unpack2(u64 d) {
    float2 r;
    asm("mov.b64 {%0, %1}, %2;" : "=f"(r.x), "=f"(r.y) : "l"(d));
    return r;
}
__device__ __forceinline__ u64 pack2(float lo, float hi) {
    u64 d;
    asm("mov.b64 %0, {%1, %2};" : "=l"(d) : "f"(lo), "f"(hi));
    return d;
}
__device__ __forceinline__ u64 pack_dup(float e) {
    u64 d;
    asm("mov.b64 %0, {%1, %1};" : "=l"(d) : "f"(e));
    return d;
}
__device__ __forceinline__ float ex2(float x) {
    float y;
    asm("ex2.approx.ftz.f32 %0, %1;" : "=f"(y) : "f"(x));
    return y;
}

/* ---- feature math ----
 * qlayer(x, phi)_w = prod_{u<=w} cos(x_u+phi_u)  (w>=1),
 * qlayer_0 = prod_{u=1..7} cos(x_u+phi_u).
 * Factorized similarity: sim = (Fa_q.Fa_k)*(Fb_q.Fb_k),
 * Fa/Fb from half-angles of qlayer outputs 0..3.
 */
__device__ __forceinline__ void load_x8(const float* __restrict__ x, int tok, float xv[8]) {
    const float4* xp = reinterpret_cast<const float4*>(x + (size_t)tok * 8);
    float4 xa = xp[0], xb = xp[1];
    xv[0] = xa.x; xv[1] = xa.y; xv[2] = xa.z; xv[3] = xa.w;
    xv[4] = xb.x; xv[5] = xb.y; xv[6] = xb.z; xv[7] = xb.w;
}

__device__ __forceinline__ void qk_features(const float xv[8], const float* __restrict__ ph,
                                            float Fa[4], float Fb[4]) {
    float c[8];
#pragma unroll
    for (int u = 0; u < 8; u++) c[u] = __cosf(xv[u] + __ldg(&ph[u]));
    float q1 = c[0] * c[1];
    float q2 = q1 * c[2];
    float q3 = q2 * c[3];
    float q0 = c[1] * c[2] * c[3] * c[4] * c[5] * c[6] * c[7];
    float s0, s1, s2, s3, a0, a1, a2, a3;
    __sincosf(0.5f * q0, &s0, &a0);
    __sincosf(0.5f * q1, &s1, &a1);
    __sincosf(0.5f * q2, &s2, &a2);
    __sincosf(0.5f * q3, &s3, &a3);
    Fa[0] = a0 * a1; Fa[1] = s0 * a1; Fa[2] = a0 * s1; Fa[3] = s0 * s1;
    Fb[0] = a2 * a3; Fb[1] = s2 * a3; Fb[2] = a2 * s3; Fb[3] = s2 * s3;
}

/* ---------------- Single fused kernel ----------------
 * Phase A: recompute K/V features for this CTA's 128-key chunk into smem
 *          (pair-interleaved packed layout) + Q features into registers.
 * Phase B: scalar packed-f32x2 mainloop (unchanged from the 45us version).
 * Phase C: write split partials; last-arriving CTA per (b,qtile) combines
 *          all KSPLIT splits and applies the output projection.
 */
__global__ __launch_bounds__(NTHR) void attn_fused_kernel(
        const float* __restrict__ x,
        const float* __restrict__ phi_q,
        const float* __restrict__ phi_k,
        const float* __restrict__ phi_v,
        const float* __restrict__ W,
        const float* __restrict__ bias,
        float* __restrict__ out) {
    __shared__ ulonglong2 sK[TK / 2 * 4];   /* 64 key-pairs x 8 comps packed = 4KB */
    __shared__ ulonglong2 sV[TK / 2 * 4];   /* 64 key-pairs x 8 comps packed = 4KB */
    __shared__ unsigned int s_old;

    const int b  = blockIdx.z;
    const int ks = blockIdx.y;
    const int qt = blockIdx.x;
    const int tid = threadIdx.x;
    const int qA = qt * QPC + tid;          /* query A (within batch) */
    const int qB = qA + NTHR;               /* query B */

    /* ---- Phase A: features ---- */
    {
        /* K + V features for key token (this thread's key) */
        float xv[8];
        load_x8(x, b * SN + ks * KCHUNK + tid, xv);
        float Fa[4], Fb[4];
        qk_features(xv, phi_k, Fa, Fb);
        float* skf = reinterpret_cast<float*>(sK);
        float* svf = reinterpret_cast<float*>(sV);
        const int p = tid >> 1, lane = tid & 1;
#pragma unroll
        for (int c = 0; c < 4; c++) skf[p * 16 + c * 2 + lane] = Fa[c];
#pragma unroll
        for (int c = 0; c < 4; c++) skf[p * 16 + (4 + c) * 2 + lane] = Fb[c];

        float cc[8];
#pragma unroll
        for (int u = 0; u < 8; u++) cc[u] = __cosf(xv[u] + __ldg(&phi_v[u]));
        float v[8];
        v[1] = cc[0] * cc[1];
#pragma unroll
        for (int w = 2; w < 8; w++) v[w] = v[w - 1] * cc[w];
        v[0] = cc[1] * cc[2] * cc[3] * cc[4] * cc[5] * cc[6] * cc[7];
#pragma unroll
        for (int c = 0; c < 8; c++) svf[p * 16 + c * 2 + lane] = v[c];
    }

    /* Q features for this thread's two queries (Fa prescaled by log2e) */
    u64 qa[8], qb[8];
    {
        float xv[8], Fa[4], Fb[4];
        load_x8(x, b * SN + qA, xv);
        qk_features(xv, phi_q, Fa, Fb);
#pragma unroll
        for (int i = 0; i < 4; i++) qa[i] = pack_dup(Fa[i] * LOG2E);
#pragma unroll
        for (int i = 0; i < 4; i++) qa[4 + i] = pack_dup(Fb[i]);
        load_x8(x, b * SN + qB, xv);
        qk_features(xv, phi_q, Fa, Fb);
#pragma unroll
        for (int i = 0; i < 4; i++) qb[i] = pack_dup(Fa[i] * LOG2E);
#pragma unroll
        for (int i = 0; i < 4; i++) qb[4 + i] = pack_dup(Fb[i]);
    }

    u64 denA = 0ull, denB = 0ull;
    u64 accA[8], accB[8];
#pragma unroll
    for (int i = 0; i < 8; i++) { accA[i] = 0ull; accB[i] = 0ull; }

    __syncthreads();

    /* ---- Phase B: mainloop (unchanged) ---- */
#pragma unroll 4
    for (int jp = 0; jp < TK / 2; jp++) {
        const ulonglong2 K01 = sK[jp * 4 + 0];
        const ulonglong2 K23 = sK[jp * 4 + 1];
        const ulonglong2 K45 = sK[jp * 4 + 2];
        const ulonglong2 K67 = sK[jp * 4 + 3];

        u64 daA = mul2(qa[0], K01.x);
        u64 daB = mul2(qb[0], K01.x);
        daA = fma2(qa[1], K01.y, daA);  daB = fma2(qb[1], K01.y, daB);
        daA = fma2(qa[2], K23.x, daA);  daB = fma2(qb[2], K23.x, daB);
        daA = fma2(qa[3], K23.y, daA);  daB = fma2(qb[3], K23.y, daB);
        u64 dbA = mul2(qa[4], K45.x);
        u64 dbB = mul2(qb[4], K45.x);
        dbA = fma2(qa[5], K45.y, dbA);  dbB = fma2(qb[5], K45.y, dbB);
        dbA = fma2(qa[6], K67.x, dbA);  dbB = fma2(qb[6], K67.x, dbB);
        dbA = fma2(qa[7], K67.y, dbA);  dbB = fma2(qb[7], K67.y, dbB);
        u64 dA = mul2(daA, dbA);
        u64 dB = mul2(daB, dbB);

        float2 uA = unpack2(dA);
        float2 uB = unpack2(dB);
        u64 eA2 = pack2(ex2(fabsf(uA.x)), ex2(fabsf(uA.y)));
        u64 eB2 = pack2(ex2(fabsf(uB.x)), ex2(fabsf(uB.y)));
        denA = add2(denA, eA2);
        denB = add2(denB, eB2);

        const ulonglong2 V01 = sV[jp * 4 + 0];
        const ulonglong2 V23 = sV[jp * 4 + 1];
        const ulonglong2 V45 = sV[jp * 4 + 2];
        const ulonglong2 V67 = sV[jp * 4 + 3];
        accA[0] = fma2(eA2, V01.x, accA[0]);  accB[0] = fma2(eB2, V01.x, accB[0]);
        accA[1] = fma2(eA2, V01.y, accA[1]);  accB[1] = fma2(eB2, V01.y, accB[1]);
        accA[2] = fma2(eA2, V23.x, accA[2]);  accB[2] = fma2(eB2, V23.x, accB[2]);
        accA[3] = fma2(eA2, V23.y, accA[3]);  accB[3] = fma2(eB2, V23.y, accB[3]);
        accA[4] = fma2(eA2, V45.x, accA[4]);  accB[4] = fma2(eB2, V45.x, accB[4]);
        accA[5] = fma2(eA2, V45.y, accA[5]);  accB[5] = fma2(eB2, V45.y, accB[5]);
        accA[6] = fma2(eA2, V67.x, accA[6]);  accB[6] = fma2(eB2, V67.x, accB[6]);
        accA[7] = fma2(eA2, V67.y, accA[7]);  accB[7] = fma2(eB2, V67.y, accB[7]);
    }

    /* ---- Phase C: partials + last-CTA finalize ---- */
    {
        float2 dA = unpack2(denA);
        float2 dB = unpack2(denB);
        g_den[(size_t)(b * SN + qA) * KSPLIT + ks] = dA.x + dA.y;
        g_den[(size_t)(b * SN + qB) * KSPLIT + ks] = dB.x + dB.y;
        float na[8], nb[8];
#pragma unroll
        for (int c = 0; c < 8; c++) {
            float2 a = unpack2(accA[c]);
            float2 bb = unpack2(accB[c]);
            na[c] = a.x + a.y;
            nb[c] = bb.x + bb.y;
        }
        float4* oa = reinterpret_cast<float4*>(g_num + ((size_t)(b * SN + qA) * KSPLIT + ks) * 8);
        float4* ob = reinterpret_cast<float4*>(g_num + ((size_t)(b * SN + qB) * KSPLIT + ks) * 8);
        oa[0] = make_float4(na[0], na[1], na[2], na[3]);
        oa[1] = make_float4(na[4], na[5], na[6], na[7]);
        ob[0] = make_float4(nb[0], nb[1], nb[2], nb[3]);
        ob[1] = make_float4(nb[4], nb[5], nb[6], nb[7]);
    }

    __threadfence();
    if (tid == 0) s_old = atomicAdd(&g_cnt[b * NQT + qt], 1u);
    __syncthreads();

    if (s_old == KSPLIT - 1) {
        /* this CTA is last for (b, qtile): combine splits + project */
#pragma unroll
        for (int h = 0; h < 2; h++) {
            const int t = b * SN + qA + h * NTHR;
            float den = 0.f, num[8];
#pragma unroll
            for (int e = 0; e < 8; e++) num[e] = 0.f;
#pragma unroll
            for (int s = 0; s < KSPLIT; s++) {
                den += g_den[(size_t)t * KSPLIT + s];
                const float4* p = reinterpret_cast<const float4*>(
                    g_num + ((size_t)t * KSPLIT + s) * 8);
                float4 p0 = p[0], p1 = p[1];
                num[0] += p0.x; num[1] += p0.y; num[2] += p0.z; num[3] += p0.w;
                num[4] += p1.x; num[5] += p1.y; num[6] += p1.z; num[7] += p1.w;
            }
            float inv = 1.0f / den;
            float o[8];
#pragma unroll
            for (int e = 0; e < 8; e++) o[e] = num[e] * inv;
#pragma unroll
            for (int d = 0; d < 8; d++) {
                float y = __ldg(&bias[d]);
#pragma unroll
                for (int e = 0; e < 8; e++) y += o[e] * __ldg(&W[d * 8 + e]);
                out[(size_t)t * 8 + d] = y;
            }
        }
        if (tid == 0) g_cnt[b * NQT + qt] = 0;   /* reset for next replay */
    }
}

extern "C" void kernel_launch(void* const* d_in, const int* in_sizes, int n_in,
                              void* d_out, int out_size) {
    const float* x     = (const float*)d_in[0];
    const float* phi_q = (const float*)d_in[1];
    const float* phi_k = (const float*)d_in[2];
    const float* phi_v = (const float*)d_in[3];
    const float* W     = (const float*)d_in[4];
    const float* bias  = (const float*)d_in[5];
    float* out = (float*)d_out;

    dim3 grid(NQT, KSPLIT, BN);
    attn_fused_kernel<<<grid, NTHR>>>(x, phi_q, phi_k, phi_v, W, bias, out);
}

// round 10
// speedup vs baseline: 2.0290x; 2.0290x over previous
#include <cuda_runtime.h>
#include <cuda_bf16.h>
#include <cstdint>

#define BN 8
#define SN 2048
#define NTOK (BN*SN)
#define KSPLIT 16
#define KCHUNK 128            /* keys per chunk == blockIdx.y granularity */
#define NTHR 256              /* 8 warps; warp = 16 queries x 128 keys */
#define QPC 128               /* queries per CTA */
#define LOG2E 1.4426950408889634f

/* Scratch (allocation-free rule: device globals), all in MMA-fragment order:
 * g_Qf: [wt = tok/16][lane][8]  a-reg order (tf32, *log2e)
 * g_Kf: [chunk = tok/128][tile = 16][lane][4]  b-frag words (tf32)
 * g_Vf: [chunk][s = 8][lane][2]  bf16x2 b-frag words for PV
 */
__device__ float    g_Qf[(size_t)NTOK * 16];
__device__ float    g_Kf[(size_t)NTOK * 16];
__device__ uint32_t g_Vf[(size_t)NTOK * 4];
__device__ float    g_den[(size_t)NTOK * KSPLIT];
__device__ float    g_num[(size_t)NTOK * KSPLIT * 8];

__device__ __forceinline__ float ex2f(float x) {
    float y; asm("ex2.approx.ftz.f32 %0, %1;" : "=f"(y) : "f"(x)); return y;
}
__device__ __forceinline__ float tf32r(float x) {
    uint32_t u; asm("cvt.rna.tf32.f32 %0, %1;" : "=r"(u) : "f"(x));
    return __uint_as_float(u);
}
/* pack (lo,hi) -> bf16x2 word, lo in low half */
__device__ __forceinline__ uint32_t bf2(float lo, float hi) {
    uint32_t r; asm("cvt.rn.bf16x2.f32 %0, %1, %2;" : "=r"(r) : "f"(hi), "f"(lo)); return r;
}

/* tf32 m16n8k8: D += A*B  (fragment layouts verified in round 5) */
__device__ __forceinline__ void mma_tf32(float c[4], uint32_t a0, uint32_t a1,
                                         uint32_t a2, uint32_t a3,
                                         uint32_t b0, uint32_t b1) {
    asm("mma.sync.aligned.m16n8k8.row.col.f32.tf32.tf32.f32 "
        "{%0,%1,%2,%3}, {%4,%5,%6,%7}, {%8,%9}, {%0,%1,%2,%3};"
        : "+f"(c[0]), "+f"(c[1]), "+f"(c[2]), "+f"(c[3])
        : "r"(a0), "r"(a1), "r"(a2), "r"(a3), "r"(b0), "r"(b1));
}
/* bf16 m16n8k16: D += A*B */
__device__ __forceinline__ void mma_bf16(float c[4], uint32_t a0, uint32_t a1,
                                         uint32_t a2, uint32_t a3,
                                         uint32_t b0, uint32_t b1) {
    asm("mma.sync.aligned.m16n8k16.row.col.f32.bf16.bf16.f32 "
        "{%0,%1,%2,%3}, {%4,%5,%6,%7}, {%8,%9}, {%0,%1,%2,%3};"
        : "+f"(c[0]), "+f"(c[1]), "+f"(c[2]), "+f"(c[3])
        : "r"(a0), "r"(a1), "r"(a2), "r"(a3), "r"(b0), "r"(b1));
}

/* ---------------- Kernel 1: features -> fragment-ordered buffers ---------------- */
__device__ __forceinline__ void load_x8(const float* __restrict__ x, int tok, float xv[8]) {
    const float4* xp = reinterpret_cast<const float4*>(x + (size_t)tok * 8);
    float4 xa = xp[0], xb = xp[1];
    xv[0]=xa.x; xv[1]=xa.y; xv[2]=xa.z; xv[3]=xa.w;
    xv[4]=xb.x; xv[5]=xb.y; xv[6]=xb.z; xv[7]=xb.w;
}

__device__ __forceinline__ void qk_features16(const float xv[8], const float* __restrict__ ph,
                                              float F[16]) {
    float c[8];
#pragma unroll
    for (int u = 0; u < 8; u++) c[u] = __cosf(xv[u] + __ldg(&ph[u]));
    float q1 = c[0]*c[1], q2 = q1*c[2], q3 = q2*c[3];
    float q0 = c[1]*c[2]*c[3]*c[4]*c[5]*c[6]*c[7];
    float s0,s1,s2,s3,a0,a1,a2,a3;
    __sincosf(0.5f*q0, &s0, &a0);
    __sincosf(0.5f*q1, &s1, &a1);
    __sincosf(0.5f*q2, &s2, &a2);
    __sincosf(0.5f*q3, &s3, &a3);
    float t01[4] = {a0*a1, s0*a1, a0*s1, s0*s1};
    float t23[4] = {a2*a3, s2*a3, a2*s3, s2*s3};
#pragma unroll
    for (int m = 0; m < 16; m++) F[m] = t01[m & 3] * t23[m >> 2];
}

__global__ void features_kernel(const float* __restrict__ x,
                                const float* __restrict__ phi_q,
                                const float* __restrict__ phi_k,
                                const float* __restrict__ phi_v) {
    int t = blockIdx.x * blockDim.x + threadIdx.x;
    if (t >= NTOK) return;
    const int kind = blockIdx.y;

    float xv[8];
    load_x8(x, t, xv);

    if (kind == 0) {
        /* Q a-reg order: [wt][lane = (gg&7)*4+t4][idx = (f>>2)*2 + (gg>>3)] */
        float F[16];
        qk_features16(xv, phi_q, F);
        const int wt = t >> 4, gg = t & 15;
        float* base = g_Qf + (size_t)wt * 256 + (size_t)((gg & 7) * 4) * 8 + (gg >> 3);
#pragma unroll
        for (int f = 0; f < 16; f++)
            base[(size_t)(f & 3) * 8 + (f >> 2) * 2] = tf32r(F[f] * LOG2E);
    } else if (kind == 1) {
        /* K b-frag order: [chunk][tile = (kk&127)>>3][lane = (kk&7)*4+t4][r = f>>2] */
        float F[16];
        qk_features16(xv, phi_k, F);
        const int chunk = t >> 7, j = (t & 127) >> 3, g = t & 7;
        float* base = g_Kf + (size_t)chunk * 2048 + (size_t)j * 128 + (size_t)(g * 4) * 4;
#pragma unroll
        for (int f = 0; f < 16; f++)
            base[(size_t)(f & 3) * 4 + (f >> 2)] = tf32r(F[f]);
    } else {
        /* V: all 8 qlayer outputs; bf16 pair-words in PV b-frag order:
         * word(chunk, s, lane=(comp*4+t4), w) = (V[key 16s+2(t4+4w)][comp],
         *                                        V[key 16s+2(t4+4w)+1][comp]) */
        float c[8];
#pragma unroll
        for (int u = 0; u < 8; u++) c[u] = __cosf(xv[u] + __ldg(&phi_v[u]));
        float v[8];
        v[1] = c[0]*c[1];
#pragma unroll
        for (int w = 2; w < 8; w++) v[w] = v[w-1]*c[w];
        v[0] = c[1]*c[2]*c[3]*c[4]*c[5]*c[6]*c[7];
        const int chunk = t >> 7, kq = t & 127;
        const int p = kq >> 1, h = kq & 1;
        const int s = p >> 3, rem = p & 7;
        const int w = rem >> 2, t4 = rem & 3;
        char* cb = reinterpret_cast<char*>(g_Vf + (size_t)chunk * 512 + (size_t)s * 64);
#pragma unroll
        for (int cc = 0; cc < 8; cc++) {
            size_t word = (size_t)(cc * 4 + t4) * 2 + w;
            *reinterpret_cast<__nv_bfloat16*>(cb + word * 4 + h * 2) = __float2bfloat16(v[cc]);
        }
    }
}

/* ---------------- Kernel 2: mma.sync flash attention partials ----------------
 * Warp = 16 queries x 128 keys. S = Q.K^T via tf32 m16n8k8 (x2 k-steps);
 * exp'd scores packed as bf16 A-frags feed PV via m16n8k16 -- no scalar PV.
 */
__global__ __launch_bounds__(NTHR) void attn_mma_kernel() {
    __shared__ float    sKf[2048];   /* 8KB: 16 tiles x 32 lanes x 4 words */
    __shared__ uint32_t sVf[512];    /* 2KB: 8 s x 32 lanes x 2 words */

    const int b  = blockIdx.z;
    const int ks = blockIdx.y;
    const int qt = blockIdx.x;
    const int tid = threadIdx.x;
    const int w = tid >> 5, l = tid & 31;
    const int g = l >> 2, t4 = l & 3;
    const int chunk = b * KSPLIT + ks;

    /* fill smem (coalesced straight copies; data already fragment-ordered) */
    {
        const float4* kg = reinterpret_cast<const float4*>(g_Kf + (size_t)chunk * 2048);
        float4* sk4 = reinterpret_cast<float4*>(sKf);
#pragma unroll
        for (int i = 0; i < 2; i++) sk4[tid + i * NTHR] = kg[tid + i * NTHR];
        if (tid < 128) {
            const uint4* vg = reinterpret_cast<const uint4*>(g_Vf + (size_t)chunk * 512);
            reinterpret_cast<uint4*>(sVf)[tid] = vg[tid];
        }
    }

    /* Q a-regs (2 k-steps x 4 regs), straight from fragment-ordered gmem */
    uint32_t qa[8];
    {
        const int wt = b * 128 + qt * 8 + w;
        const float4* qp = reinterpret_cast<const float4*>(
            g_Qf + (size_t)wt * 256 + (size_t)l * 8);
        float4 q0 = qp[0], q1 = qp[1];
        qa[0]=__float_as_uint(q0.x); qa[1]=__float_as_uint(q0.y);
        qa[2]=__float_as_uint(q0.z); qa[3]=__float_as_uint(q0.w);
        qa[4]=__float_as_uint(q1.x); qa[5]=__float_as_uint(q1.y);
        qa[6]=__float_as_uint(q1.z); qa[7]=__float_as_uint(q1.w);
    }

    float o[4] = {0.f, 0.f, 0.f, 0.f};
    float den0 = 0.f, den1 = 0.f;

    __syncthreads();

#pragma unroll
    for (int s = 0; s < 8; s++) {
        /* K b-frags for S tiles 2s, 2s+1 (conflict-free LDS.128) */
        const float4 kb0 = *reinterpret_cast<const float4*>(&sKf[(2*s)     * 128 + l * 4]);
        const float4 kb1 = *reinterpret_cast<const float4*>(&sKf[(2*s + 1) * 128 + l * 4]);

        float c0[4] = {0.f,0.f,0.f,0.f}, c1[4] = {0.f,0.f,0.f,0.f};
        mma_tf32(c0, qa[0],qa[1],qa[2],qa[3], __float_as_uint(kb0.x), __float_as_uint(kb0.y));
        mma_tf32(c0, qa[4],qa[5],qa[6],qa[7], __float_as_uint(kb0.z), __float_as_uint(kb0.w));
        mma_tf32(c1, qa[0],qa[1],qa[2],qa[3], __float_as_uint(kb1.x), __float_as_uint(kb1.y));
        mma_tf32(c1, qa[4],qa[5],qa[6],qa[7], __float_as_uint(kb1.z), __float_as_uint(kb1.w));

        /* exp (scores pre-scaled by log2e in Q features) */
        float e00 = ex2f(fabsf(c0[0])), e01 = ex2f(fabsf(c0[1]));
        float e02 = ex2f(fabsf(c0[2])), e03 = ex2f(fabsf(c0[3]));
        float e10 = ex2f(fabsf(c1[0])), e11 = ex2f(fabsf(c1[1]));
        float e12 = ex2f(fabsf(c1[2])), e13 = ex2f(fabsf(c1[3]));
        den0 += (e00 + e01) + (e10 + e11);
        den1 += (e02 + e03) + (e12 + e13);

        /* S C-frag -> PV A-frag (bf16), keys 16s..16s+15 */
        uint32_t pa0 = bf2(e00, e01);   /* row g,   k 2t4,2t4+1   */
        uint32_t pa1 = bf2(e02, e03);   /* row g+8, k 2t4,2t4+1   */
        uint32_t pa2 = bf2(e10, e11);   /* row g,   k 2t4+8,+9    */
        uint32_t pa3 = bf2(e12, e13);   /* row g+8, k 2t4+8,+9    */

        const uint2 vb = *reinterpret_cast<const uint2*>(&sVf[s * 64 + l * 2]);
        mma_bf16(o, pa0, pa1, pa2, pa3, vb.x, vb.y);
    }

    /* den: reduce across the 4 t4 lanes sharing each row */
    den0 += __shfl_xor_sync(0xffffffffu, den0, 1);
    den0 += __shfl_xor_sync(0xffffffffu, den0, 2);
    den1 += __shfl_xor_sync(0xffffffffu, den1, 1);
    den1 += __shfl_xor_sync(0xffffffffu, den1, 2);

    /* write partials: o C-frag is complete (comps 2t4,2t4+1 per row) */
    const int tokA = b * SN + qt * QPC + w * 16 + g;
    const int tokB = tokA + 8;
    reinterpret_cast<float2*>(g_num + ((size_t)tokA * KSPLIT + ks) * 8)[t4] =
        make_float2(o[0], o[1]);
    reinterpret_cast<float2*>(g_num + ((size_t)tokB * KSPLIT + ks) * 8)[t4] =
        make_float2(o[2], o[3]);
    if (t4 == 0) {
        g_den[(size_t)tokA * KSPLIT + ks] = den0;
        g_den[(size_t)tokB * KSPLIT + ks] = den1;
    }
}

/* ---------------- Kernel 3: combine splits + output projection ---------------- */
__global__ void finalize_kernel(const float* __restrict__ W,
                                const float* __restrict__ bias,
                                float* __restrict__ out) {
    int t = blockIdx.x * blockDim.x + threadIdx.x;
    if (t >= NTOK) return;

    float den = 0.f, num[8];
#pragma unroll
    for (int e = 0; e < 8; e++) num[e] = 0.f;
#pragma unroll
    for (int ks = 0; ks < KSPLIT; ks++) {
        den += g_den[(size_t)t * KSPLIT + ks];
        const float4* p = reinterpret_cast<const float4*>(g_num + ((size_t)t * KSPLIT + ks) * 8);
        float4 p0 = p[0], p1 = p[1];
        num[0] += p0.x; num[1] += p0.y; num[2] += p0.z; num[3] += p0.w;
        num[4] += p1.x; num[5] += p1.y; num[6] += p1.z; num[7] += p1.w;
    }
    float inv = 1.0f / den;
    float o[8];
#pragma unroll
    for (int e = 0; e < 8; e++) o[e] = num[e] * inv;

#pragma unroll
    for (int d = 0; d < 8; d++) {
        float y = __ldg(&bias[d]);
#pragma unroll
        for (int e = 0; e < 8; e++) y += o[e] * __ldg(&W[d * 8 + e]);
        out[(size_t)t * 8 + d] = y;
    }
}

extern "C" void kernel_launch(void* const* d_in, const int* in_sizes, int n_in,
                              void* d_out, int out_size) {
    const float* x     = (const float*)d_in[0];
    const float* phi_q = (const float*)d_in[1];
    const float* phi_k = (const float*)d_in[2];
    const float* phi_v = (const float*)d_in[3];
    const float* W     = (const float*)d_in[4];
    const float* bias  = (const float*)d_in[5];
    float* out = (float*)d_out;

    dim3 fgrid(NTOK / 128, 3);
    features_kernel<<<fgrid, 128>>>(x, phi_q, phi_k, phi_v);

    dim3 grid(SN / QPC, KSPLIT, BN);
    attn_mma_kernel<<<grid, NTHR>>>();

    finalize_kernel<<<NTOK / 256, 256>>>(W, bias, out);
}

// round 11
// speedup vs baseline: 2.1362x; 1.0528x over previous
#include <cuda_runtime.h>
#include <cuda_bf16.h>
#include <cstdint>

#define BN 8
#define SN 2048
#define NTOK (BN*SN)
#define KSPLIT 16
#define KCHUNK 128            /* keys per chunk == blockIdx.y granularity */
#define NTHR 256              /* 8 warps; warp = 16 queries x 128 keys */
#define QPC 128               /* queries per CTA */
#define LOG2E 1.4426950408889634f

/* Scratch (allocation-free rule: device globals), all in MMA-fragment order:
 * g_Qf: [wt = tok/16][lane][8]  a-reg order (tf32, *log2e)
 * g_Kf: [chunk = tok/128][tile = 16][lane][4]  b-frag words (tf32)
 * g_Vf: [chunk][s = 8][lane][2]  bf16x2 b-frag words for PV
 */
__device__ float    g_Qf[(size_t)NTOK * 16];
__device__ float    g_Kf[(size_t)NTOK * 16];
__device__ uint32_t g_Vf[(size_t)NTOK * 4];
__device__ float    g_den[(size_t)NTOK * KSPLIT];
__device__ float    g_num[(size_t)NTOK * KSPLIT * 8];

__device__ __forceinline__ float ex2f(float x) {
    float y; asm("ex2.approx.ftz.f32 %0, %1;" : "=f"(y) : "f"(x)); return y;
}
__device__ __forceinline__ float tf32r(float x) {
    uint32_t u; asm("cvt.rna.tf32.f32 %0, %1;" : "=r"(u) : "f"(x));
    return __uint_as_float(u);
}
/* pack (lo,hi) -> bf16x2 word, lo in low half */
__device__ __forceinline__ uint32_t bf2(float lo, float hi) {
    uint32_t r; asm("cvt.rn.bf16x2.f32 %0, %1, %2;" : "=r"(r) : "f"(hi), "f"(lo)); return r;
}

/* tf32 m16n8k8: D += A*B  (fragment layouts verified in rounds 5/10) */
__device__ __forceinline__ void mma_tf32(float c[4], uint32_t a0, uint32_t a1,
                                         uint32_t a2, uint32_t a3,
                                         uint32_t b0, uint32_t b1) {
    asm("mma.sync.aligned.m16n8k8.row.col.f32.tf32.tf32.f32 "
        "{%0,%1,%2,%3}, {%4,%5,%6,%7}, {%8,%9}, {%0,%1,%2,%3};"
        : "+f"(c[0]), "+f"(c[1]), "+f"(c[2]), "+f"(c[3])
        : "r"(a0), "r"(a1), "r"(a2), "r"(a3), "r"(b0), "r"(b1));
}
/* bf16 m16n8k16: D += A*B */
__device__ __forceinline__ void mma_bf16(float c[4], uint32_t a0, uint32_t a1,
                                         uint32_t a2, uint32_t a3,
                                         uint32_t b0, uint32_t b1) {
    asm("mma.sync.aligned.m16n8k16.row.col.f32.bf16.bf16.f32 "
        "{%0,%1,%2,%3}, {%4,%5,%6,%7}, {%8,%9}, {%0,%1,%2,%3};"
        : "+f"(c[0]), "+f"(c[1]), "+f"(c[2]), "+f"(c[3])
        : "r"(a0), "r"(a1), "r"(a2), "r"(a3), "r"(b0), "r"(b1));
}

/* ---------------- Kernel 1: features -> fragment-ordered buffers ----------------
 * One 128-thread block per 128-token chunk; fragment scatter goes through smem
 * (STS), then a linear coalesced float4 copy-out (STG.128).
 */
__device__ __forceinline__ void load_x8(const float* __restrict__ x, int tok, float xv[8]) {
    const float4* xp = reinterpret_cast<const float4*>(x + (size_t)tok * 8);
    float4 xa = xp[0], xb = xp[1];
    xv[0]=xa.x; xv[1]=xa.y; xv[2]=xa.z; xv[3]=xa.w;
    xv[4]=xb.x; xv[5]=xb.y; xv[6]=xb.z; xv[7]=xb.w;
}

__device__ __forceinline__ void qk_features16(const float xv[8], const float* __restrict__ ph,
                                              float F[16]) {
    float c[8];
#pragma unroll
    for (int u = 0; u < 8; u++) c[u] = __cosf(xv[u] + __ldg(&ph[u]));
    float q1 = c[0]*c[1], q2 = q1*c[2], q3 = q2*c[3];
    float q0 = c[1]*c[2]*c[3]*c[4]*c[5]*c[6]*c[7];
    float s0,s1,s2,s3,a0,a1,a2,a3;
    __sincosf(0.5f*q0, &s0, &a0);
    __sincosf(0.5f*q1, &s1, &a1);
    __sincosf(0.5f*q2, &s2, &a2);
    __sincosf(0.5f*q3, &s3, &a3);
    float t01[4] = {a0*a1, s0*a1, a0*s1, s0*s1};
    float t23[4] = {a2*a3, s2*a3, a2*s3, s2*s3};
#pragma unroll
    for (int m = 0; m < 16; m++) F[m] = t01[m & 3] * t23[m >> 2];
}

__global__ __launch_bounds__(128) void features_kernel(
        const float* __restrict__ x,
        const float* __restrict__ phi_q,
        const float* __restrict__ phi_k,
        const float* __restrict__ phi_v) {
    __shared__ float st[2048];   /* 8KB staging */
    const int tid = threadIdx.x;
    const int blk = blockIdx.x;              /* 128-token chunk index */
    const int t = blk * 128 + tid;
    const int kind = blockIdx.y;

    float xv[8];
    load_x8(x, t, xv);

    if (kind == 0) {
        /* Q a-reg order: [wt][lane = (gg&7)*4+t4][word = (f>>2)*2 + (gg>>3)] */
        float F[16];
        qk_features16(xv, phi_q, F);
        const int wt_l = tid >> 4, gg = tid & 15;
        float* base = st + wt_l * 256 + ((gg & 7) * 4) * 8 + (gg >> 3);
#pragma unroll
        for (int f = 0; f < 16; f++)
            base[(f & 3) * 8 + (f >> 2) * 2] = tf32r(F[f] * LOG2E);
        __syncthreads();
        float4* dst = reinterpret_cast<float4*>(g_Qf + (size_t)blk * 2048);
        const float4* s4 = reinterpret_cast<const float4*>(st);
#pragma unroll
        for (int i = 0; i < 4; i++) dst[tid + i * 128] = s4[tid + i * 128];
    } else if (kind == 1) {
        /* K b-frag order: [tile = kk>>3][lane = (kk&7)*4+t4][word = f>>2] */
        float F[16];
        qk_features16(xv, phi_k, F);
        const int j = tid >> 3, g = tid & 7;
        float* base = st + j * 128 + g * 16;
#pragma unroll
        for (int f = 0; f < 16; f++)
            base[(f & 3) * 4 + (f >> 2)] = tf32r(F[f]);
        __syncthreads();
        float4* dst = reinterpret_cast<float4*>(g_Kf + (size_t)blk * 2048);
        const float4* s4 = reinterpret_cast<const float4*>(st);
#pragma unroll
        for (int i = 0; i < 4; i++) dst[tid + i * 128] = s4[tid + i * 128];
    } else {
        /* V bf16 pair-words in PV b-frag order */
        float c[8];
#pragma unroll
        for (int u = 0; u < 8; u++) c[u] = __cosf(xv[u] + __ldg(&phi_v[u]));
        float v[8];
        v[1] = c[0]*c[1];
#pragma unroll
        for (int w = 2; w < 8; w++) v[w] = v[w-1]*c[w];
        v[0] = c[1]*c[2]*c[3]*c[4]*c[5]*c[6]*c[7];
        const int kq = tid;
        const int p = kq >> 1, h = kq & 1;
        const int s = p >> 3, rem = p & 7;
        const int w = rem >> 2, t4 = rem & 3;
        char* cb = reinterpret_cast<char*>(st) + s * 256;
#pragma unroll
        for (int cc = 0; cc < 8; cc++) {
            int word = (cc * 4 + t4) * 2 + w;
            *reinterpret_cast<__nv_bfloat16*>(cb + word * 4 + h * 2) = __float2bfloat16(v[cc]);
        }
        __syncthreads();
        if (tid < 128) {
            uint4* dst = reinterpret_cast<uint4*>(g_Vf + (size_t)blk * 512);
            dst[tid] = reinterpret_cast<const uint4*>(st)[tid];
        }
    }
}

/* ---------------- Kernel 2: mma.sync flash attention partials ----------------
 * Warp = 16 queries x 128 keys. S = Q.K^T via tf32 m16n8k8 (x2 k-steps);
 * exp'd scores packed as bf16 A-frags feed PV via m16n8k16.
 * den via a second MMA against B = ones-in-col-0 (no FADD tree, no shfl).
 */
__global__ __launch_bounds__(NTHR) void attn_mma_kernel() {
    __shared__ float    sKf[2048];   /* 8KB: 16 tiles x 32 lanes x 4 words */
    __shared__ uint32_t sVf[512];    /* 2KB: 8 s x 32 lanes x 2 words */

    const int b  = blockIdx.z;
    const int ks = blockIdx.y;
    const int qt = blockIdx.x;
    const int tid = threadIdx.x;
    const int w = tid >> 5, l = tid & 31;
    const int g = l >> 2, t4 = l & 3;
    const int chunk = b * KSPLIT + ks;

    /* fill smem (coalesced straight copies; data already fragment-ordered) */
    {
        const float4* kg = reinterpret_cast<const float4*>(g_Kf + (size_t)chunk * 2048);
        float4* sk4 = reinterpret_cast<float4*>(sKf);
#pragma unroll
        for (int i = 0; i < 2; i++) sk4[tid + i * NTHR] = kg[tid + i * NTHR];
        if (tid < 128) {
            const uint4* vg = reinterpret_cast<const uint4*>(g_Vf + (size_t)chunk * 512);
            reinterpret_cast<uint4*>(sVf)[tid] = vg[tid];
        }
    }

    /* Q a-regs (2 k-steps x 4 regs), straight from fragment-ordered gmem */
    uint32_t qa[8];
    {
        const int wt = b * 128 + qt * 8 + w;
        const float4* qp = reinterpret_cast<const float4*>(
            g_Qf + (size_t)wt * 256 + (size_t)l * 8);
        float4 q0 = qp[0], q1 = qp[1];
        qa[0]=__float_as_uint(q0.x); qa[1]=__float_as_uint(q0.y);
        qa[2]=__float_as_uint(q0.z); qa[3]=__float_as_uint(q0.w);
        qa[4]=__float_as_uint(q1.x); qa[5]=__float_as_uint(q1.y);
        qa[6]=__float_as_uint(q1.z); qa[7]=__float_as_uint(q1.w);
    }

    /* ones-in-col-0 B-frag for the den MMA: col n = g, rows k all */
    const uint32_t ones = (g == 0) ? 0x3F803F80u : 0u;

    float o[4]  = {0.f, 0.f, 0.f, 0.f};
    float o2[4] = {0.f, 0.f, 0.f, 0.f};

    __syncthreads();

#pragma unroll
    for (int s = 0; s < 8; s++) {
        /* K b-frags for S tiles 2s, 2s+1 (conflict-free LDS.128) */
        const float4 kb0 = *reinterpret_cast<const float4*>(&sKf[(2*s)     * 128 + l * 4]);
        const float4 kb1 = *reinterpret_cast<const float4*>(&sKf[(2*s + 1) * 128 + l * 4]);

        float c0[4] = {0.f,0.f,0.f,0.f}, c1[4] = {0.f,0.f,0.f,0.f};
        mma_tf32(c0, qa[0],qa[1],qa[2],qa[3], __float_as_uint(kb0.x), __float_as_uint(kb0.y));
        mma_tf32(c0, qa[4],qa[5],qa[6],qa[7], __float_as_uint(kb0.z), __float_as_uint(kb0.w));
        mma_tf32(c1, qa[0],qa[1],qa[2],qa[3], __float_as_uint(kb1.x), __float_as_uint(kb1.y));
        mma_tf32(c1, qa[4],qa[5],qa[6],qa[7], __float_as_uint(kb1.z), __float_as_uint(kb1.w));

        /* exp (scores pre-scaled by log2e in Q features) */
        float e00 = ex2f(fabsf(c0[0])), e01 = ex2f(fabsf(c0[1]));
        float e02 = ex2f(fabsf(c0[2])), e03 = ex2f(fabsf(c0[3]));
        float e10 = ex2f(fabsf(c1[0])), e11 = ex2f(fabsf(c1[1]));
        float e12 = ex2f(fabsf(c1[2])), e13 = ex2f(fabsf(c1[3]));

        /* S C-frag -> PV A-frag (bf16), keys 16s..16s+15 */
        uint32_t pa0 = bf2(e00, e01);   /* row g,   k 2t4,2t4+1   */
        uint32_t pa1 = bf2(e02, e03);   /* row g+8, k 2t4,2t4+1   */
        uint32_t pa2 = bf2(e10, e11);   /* row g,   k 2t4+8,+9    */
        uint32_t pa3 = bf2(e12, e13);   /* row g+8, k 2t4+8,+9    */

        const uint2 vb = *reinterpret_cast<const uint2*>(&sVf[s * 64 + l * 2]);
        mma_bf16(o, pa0, pa1, pa2, pa3, vb.x, vb.y);
        mma_bf16(o2, pa0, pa1, pa2, pa3, ones, ones);   /* den in col 0 */
    }

    /* write partials: o C-frag complete (comps 2t4,2t4+1 per row);
     * den = o2[0] (row g), o2[2] (row g+8) valid at t4==0 (col 0). */
    const int tokA = b * SN + qt * QPC + w * 16 + g;
    const int tokB = tokA + 8;
    reinterpret_cast<float2*>(g_num + ((size_t)tokA * KSPLIT + ks) * 8)[t4] =
        make_float2(o[0], o[1]);
    reinterpret_cast<float2*>(g_num + ((size_t)tokB * KSPLIT + ks) * 8)[t4] =
        make_float2(o[2], o[3]);
    if (t4 == 0) {
        g_den[(size_t)tokA * KSPLIT + ks] = o2[0];
        g_den[(size_t)tokB * KSPLIT + ks] = o2[2];
    }
}

/* ---------------- Kernel 3: combine splits + output projection ---------------- */
__global__ void finalize_kernel(const float* __restrict__ W,
                                const float* __restrict__ bias,
                                float* __restrict__ out) {
    int t = blockIdx.x * blockDim.x + threadIdx.x;
    if (t >= NTOK) return;

    float den = 0.f, num[8];
#pragma unroll
    for (int e = 0; e < 8; e++) num[e] = 0.f;
#pragma unroll
    for (int ks = 0; ks < KSPLIT; ks++) {
        den += g_den[(size_t)t * KSPLIT + ks];
        const float4* p = reinterpret_cast<const float4*>(g_num + ((size_t)t * KSPLIT + ks) * 8);
        float4 p0 = p[0], p1 = p[1];
        num[0] += p0.x; num[1] += p0.y; num[2] += p0.z; num[3] += p0.w;
        num[4] += p1.x; num[5] += p1.y; num[6] += p1.z; num[7] += p1.w;
    }
    float inv = 1.0f / den;
    float o[8];
#pragma unroll
    for (int e = 0; e < 8; e++) o[e] = num[e] * inv;

#pragma unroll
    for (int d = 0; d < 8; d++) {
        float y = __ldg(&bias[d]);
#pragma unroll
        for (int e = 0; e < 8; e++) y += o[e] * __ldg(&W[d * 8 + e]);
        out[(size_t)t * 8 + d] = y;
    }
}

extern "C" void kernel_launch(void* const* d_in, const int* in_sizes, int n_in,
                              void* d_out, int out_size) {
    const float* x     = (const float*)d_in[0];
    const float* phi_q = (const float*)d_in[1];
    const float* phi_k = (const float*)d_in[2];
    const float* phi_v = (const float*)d_in[3];
    const float* W     = (const float*)d_in[4];
    const float* bias  = (const float*)d_in[5];
    float* out = (float*)d_out;

    dim3 fgrid(NTOK / 128, 3);
    features_kernel<<<fgrid, 128>>>(x, phi_q, phi_k, phi_v);

    dim3 grid(SN / QPC, KSPLIT, BN);
    attn_mma_kernel<<<grid, NTHR>>>();

    finalize_kernel<<<NTOK / 256, 256>>>(W, bias, out);
}

// round 12
// speedup vs baseline: 2.3575x; 1.1036x over previous
#include <cuda_runtime.h>
#include <cuda_bf16.h>
#include <cstdint>

#define BN 8
#define SN 2048
#define NTOK (BN*SN)
#define KSPLIT 4
#define SUBC 4                /* 128-key chunks per CTA */
#define NTHR 256              /* 8 warps; warp = 16 queries x 128 keys */
#define QPC 128               /* queries per CTA */
#define NQT (SN/QPC)          /* 16 query tiles */
#define LOG2E 1.4426950408889634f

/* Scratch (allocation-free rule: device globals), all in MMA-fragment order:
 * g_Qf: [wt = tok/16][lane][8]  a-reg order (tf32, *log2e)
 * g_Kf: [chunk = tok/128][tile = 16][lane][4]  b-frag words (tf32)
 * g_Vf: [chunk][s = 8][lane][2]  bf16x2 b-frag words for PV
 */
__device__ float    g_Qf[(size_t)NTOK * 16];
__device__ float    g_Kf[(size_t)NTOK * 16];
__device__ uint32_t g_Vf[(size_t)NTOK * 4];
__device__ float    g_den[(size_t)NTOK * KSPLIT];
__device__ float    g_num[(size_t)NTOK * KSPLIT * 8];
__device__ unsigned int g_cnt[BN * NQT];   /* zero-init; each run returns it to 0 */

__device__ __forceinline__ float ex2f(float x) {
    float y; asm("ex2.approx.ftz.f32 %0, %1;" : "=f"(y) : "f"(x)); return y;
}
__device__ __forceinline__ float tf32r(float x) {
    uint32_t u; asm("cvt.rna.tf32.f32 %0, %1;" : "=r"(u) : "f"(x));
    return __uint_as_float(u);
}
/* pack (lo,hi) -> bf16x2 word, lo in low half */
__device__ __forceinline__ uint32_t bf2(float lo, float hi) {
    uint32_t r; asm("cvt.rn.bf16x2.f32 %0, %1, %2;" : "=r"(r) : "f"(hi), "f"(lo)); return r;
}

/* tf32 m16n8k8: D += A*B  (fragment layouts verified in rounds 5/10) */
__device__ __forceinline__ void mma_tf32(float c[4], uint32_t a0, uint32_t a1,
                                         uint32_t a2, uint32_t a3,
                                         uint32_t b0, uint32_t b1) {
    asm("mma.sync.aligned.m16n8k8.row.col.f32.tf32.tf32.f32 "
        "{%0,%1,%2,%3}, {%4,%5,%6,%7}, {%8,%9}, {%0,%1,%2,%3};"
        : "+f"(c[0]), "+f"(c[1]), "+f"(c[2]), "+f"(c[3])
        : "r"(a0), "r"(a1), "r"(a2), "r"(a3), "r"(b0), "r"(b1));
}
/* bf16 m16n8k16: D += A*B */
__device__ __forceinline__ void mma_bf16(float c[4], uint32_t a0, uint32_t a1,
                                         uint32_t a2, uint32_t a3,
                                         uint32_t b0, uint32_t b1) {
    asm("mma.sync.aligned.m16n8k16.row.col.f32.bf16.bf16.f32 "
        "{%0,%1,%2,%3}, {%4,%5,%6,%7}, {%8,%9}, {%0,%1,%2,%3};"
        : "+f"(c[0]), "+f"(c[1]), "+f"(c[2]), "+f"(c[3])
        : "r"(a0), "r"(a1), "r"(a2), "r"(a3), "r"(b0), "r"(b1));
}

/* ---------------- Kernel 1: features -> fragment-ordered buffers ---------------- */
__device__ __forceinline__ void load_x8(const float* __restrict__ x, int tok, float xv[8]) {
    const float4* xp = reinterpret_cast<const float4*>(x + (size_t)tok * 8);
    float4 xa = xp[0], xb = xp[1];
    xv[0]=xa.x; xv[1]=xa.y; xv[2]=xa.z; xv[3]=xa.w;
    xv[4]=xb.x; xv[5]=xb.y; xv[6]=xb.z; xv[7]=xb.w;
}

__device__ __forceinline__ void qk_features16(const float xv[8], const float* __restrict__ ph,
                                              float F[16]) {
    float c[8];
#pragma unroll
    for (int u = 0; u < 8; u++) c[u] = __cosf(xv[u] + __ldg(&ph[u]));
    float q1 = c[0]*c[1], q2 = q1*c[2], q3 = q2*c[3];
    float q0 = c[1]*c[2]*c[3]*c[4]*c[5]*c[6]*c[7];
    float s0,s1,s2,s3,a0,a1,a2,a3;
    __sincosf(0.5f*q0, &s0, &a0);
    __sincosf(0.5f*q1, &s1, &a1);
    __sincosf(0.5f*q2, &s2, &a2);
    __sincosf(0.5f*q3, &s3, &a3);
    float t01[4] = {a0*a1, s0*a1, a0*s1, s0*s1};
    float t23[4] = {a2*a3, s2*a3, a2*s3, s2*s3};
#pragma unroll
    for (int m = 0; m < 16; m++) F[m] = t01[m & 3] * t23[m >> 2];
}

__global__ __launch_bounds__(128) void features_kernel(
        const float* __restrict__ x,
        const float* __restrict__ phi_q,
        const float* __restrict__ phi_k,
        const float* __restrict__ phi_v) {
    __shared__ float st[2048];   /* 8KB staging */
    const int tid = threadIdx.x;
    const int blk = blockIdx.x;              /* 128-token chunk index */
    const int t = blk * 128 + tid;
    const int kind = blockIdx.y;

    float xv[8];
    load_x8(x, t, xv);

    if (kind == 0) {
        /* Q a-reg order: [wt][lane = (gg&7)*4+t4][word = (f>>2)*2 + (gg>>3)] */
        float F[16];
        qk_features16(xv, phi_q, F);
        const int wt_l = tid >> 4, gg = tid & 15;
        float* base = st + wt_l * 256 + ((gg & 7) * 4) * 8 + (gg >> 3);
#pragma unroll
        for (int f = 0; f < 16; f++)
            base[(f & 3) * 8 + (f >> 2) * 2] = tf32r(F[f] * LOG2E);
        __syncthreads();
        float4* dst = reinterpret_cast<float4*>(g_Qf + (size_t)blk * 2048);
        const float4* s4 = reinterpret_cast<const float4*>(st);
#pragma unroll
        for (int i = 0; i < 4; i++) dst[tid + i * 128] = s4[tid + i * 128];
    } else if (kind == 1) {
        /* K b-frag order: [tile = kk>>3][lane = (kk&7)*4+t4][word = f>>2] */
        float F[16];
        qk_features16(xv, phi_k, F);
        const int j = tid >> 3, g = tid & 7;
        float* base = st + j * 128 + g * 16;
#pragma unroll
        for (int f = 0; f < 16; f++)
            base[(f & 3) * 4 + (f >> 2)] = tf32r(F[f]);
        __syncthreads();
        float4* dst = reinterpret_cast<float4*>(g_Kf + (size_t)blk * 2048);
        const float4* s4 = reinterpret_cast<const float4*>(st);
#pragma unroll
        for (int i = 0; i < 4; i++) dst[tid + i * 128] = s4[tid + i * 128];
    } else {
        /* V bf16 pair-words in PV b-frag order */
        float c[8];
#pragma unroll
        for (int u = 0; u < 8; u++) c[u] = __cosf(xv[u] + __ldg(&phi_v[u]));
        float v[8];
        v[1] = c[0]*c[1];
#pragma unroll
        for (int w = 2; w < 8; w++) v[w] = v[w-1]*c[w];
        v[0] = c[1]*c[2]*c[3]*c[4]*c[5]*c[6]*c[7];
        const int kq = tid;
        const int p = kq >> 1, h = kq & 1;
        const int s = p >> 3, rem = p & 7;
        const int w = rem >> 2, t4 = rem & 3;
        char* cb = reinterpret_cast<char*>(st) + s * 256;
#pragma unroll
        for (int cc = 0; cc < 8; cc++) {
            int word = (cc * 4 + t4) * 2 + w;
            *reinterpret_cast<__nv_bfloat16*>(cb + word * 4 + h * 2) = __float2bfloat16(v[cc]);
        }
        __syncthreads();
        if (tid < 128) {
            uint4* dst = reinterpret_cast<uint4*>(g_Vf + (size_t)blk * 512);
            dst[tid] = reinterpret_cast<const uint4*>(st)[tid];
        }
    }
}

/* ---------------- Kernel 2: mma.sync flash attention + fused finalize ----------------
 * Warp = 16 queries x 512 keys (4 chunks of 128, accumulated in C-frags).
 * S = Q.K^T via tf32 m16n8k8 (x2 k-steps); exp'd scores as bf16 A-frags feed
 * PV via m16n8k16; den via ones-in-col-0 MMA. Last CTA per (b,qtile)
 * combines the KSPLIT=4 splits and applies the output projection.
 */
__global__ __launch_bounds__(NTHR) void attn_mma_kernel(
        const float* __restrict__ W,
        const float* __restrict__ bias,
        float* __restrict__ out) {
    __shared__ float    sKf[2048];   /* 8KB: 16 tiles x 32 lanes x 4 words */
    __shared__ uint32_t sVf[512];    /* 2KB: 8 s x 32 lanes x 2 words */
    __shared__ unsigned int s_old;

    const int b  = blockIdx.z;
    const int ks = blockIdx.y;
    const int qt = blockIdx.x;
    const int tid = threadIdx.x;
    const int w = tid >> 5, l = tid & 31;
    const int g = l >> 2, t4 = l & 3;

    /* Q a-regs (2 k-steps x 4 regs), loaded once per CTA */
    uint32_t qa[8];
    {
        const int wt = b * 128 + qt * 8 + w;
        const float4* qp = reinterpret_cast<const float4*>(
            g_Qf + (size_t)wt * 256 + (size_t)l * 8);
        float4 q0 = qp[0], q1 = qp[1];
        qa[0]=__float_as_uint(q0.x); qa[1]=__float_as_uint(q0.y);
        qa[2]=__float_as_uint(q0.z); qa[3]=__float_as_uint(q0.w);
        qa[4]=__float_as_uint(q1.x); qa[5]=__float_as_uint(q1.y);
        qa[6]=__float_as_uint(q1.z); qa[7]=__float_as_uint(q1.w);
    }

    /* ones-in-col-0 B-frag for the den MMA */
    const uint32_t ones = (g == 0) ? 0x3F803F80u : 0u;

    float o[4]  = {0.f, 0.f, 0.f, 0.f};
    float o2[4] = {0.f, 0.f, 0.f, 0.f};

    for (int c4 = 0; c4 < SUBC; c4++) {
        const int chunk = b * 16 + ks * SUBC + c4;
        __syncthreads();
        {
            const float4* kg = reinterpret_cast<const float4*>(g_Kf + (size_t)chunk * 2048);
            float4* sk4 = reinterpret_cast<float4*>(sKf);
#pragma unroll
            for (int i = 0; i < 2; i++) sk4[tid + i * NTHR] = kg[tid + i * NTHR];
            if (tid < 128) {
                const uint4* vg = reinterpret_cast<const uint4*>(g_Vf + (size_t)chunk * 512);
                reinterpret_cast<uint4*>(sVf)[tid] = vg[tid];
            }
        }
        __syncthreads();

#pragma unroll
        for (int s = 0; s < 8; s++) {
            const float4 kb0 = *reinterpret_cast<const float4*>(&sKf[(2*s)     * 128 + l * 4]);
            const float4 kb1 = *reinterpret_cast<const float4*>(&sKf[(2*s + 1) * 128 + l * 4]);

            float c0[4] = {0.f,0.f,0.f,0.f}, c1[4] = {0.f,0.f,0.f,0.f};
            mma_tf32(c0, qa[0],qa[1],qa[2],qa[3], __float_as_uint(kb0.x), __float_as_uint(kb0.y));
            mma_tf32(c0, qa[4],qa[5],qa[6],qa[7], __float_as_uint(kb0.z), __float_as_uint(kb0.w));
            mma_tf32(c1, qa[0],qa[1],qa[2],qa[3], __float_as_uint(kb1.x), __float_as_uint(kb1.y));
            mma_tf32(c1, qa[4],qa[5],qa[6],qa[7], __float_as_uint(kb1.z), __float_as_uint(kb1.w));

            float e00 = ex2f(fabsf(c0[0])), e01 = ex2f(fabsf(c0[1]));
            float e02 = ex2f(fabsf(c0[2])), e03 = ex2f(fabsf(c0[3]));
            float e10 = ex2f(fabsf(c1[0])), e11 = ex2f(fabsf(c1[1]));
            float e12 = ex2f(fabsf(c1[2])), e13 = ex2f(fabsf(c1[3]));

            uint32_t pa0 = bf2(e00, e01);
            uint32_t pa1 = bf2(e02, e03);
            uint32_t pa2 = bf2(e10, e11);
            uint32_t pa3 = bf2(e12, e13);

            const uint2 vb = *reinterpret_cast<const uint2*>(&sVf[s * 64 + l * 2]);
            mma_bf16(o, pa0, pa1, pa2, pa3, vb.x, vb.y);
            mma_bf16(o2, pa0, pa1, pa2, pa3, ones, ones);   /* den in col 0 */
        }
    }

    /* write partials: o C-frag complete (comps 2t4,2t4+1 per row);
     * den = o2[0] (row g), o2[2] (row g+8) valid at t4==0 (col 0). */
    const int tokA = b * SN + qt * QPC + w * 16 + g;
    const int tokB = tokA + 8;
    reinterpret_cast<float2*>(g_num + ((size_t)tokA * KSPLIT + ks) * 8)[t4] =
        make_float2(o[0], o[1]);
    reinterpret_cast<float2*>(g_num + ((size_t)tokB * KSPLIT + ks) * 8)[t4] =
        make_float2(o[2], o[3]);
    if (t4 == 0) {
        g_den[(size_t)tokA * KSPLIT + ks] = o2[0];
        g_den[(size_t)tokB * KSPLIT + ks] = o2[2];
    }

    /* ---- fused finalize: last-arriving CTA per (b,qt) ---- */
    __threadfence();
    if (tid == 0) s_old = atomicAdd(&g_cnt[b * NQT + qt], 1u);
    __syncthreads();

    if (s_old == KSPLIT - 1) {
        if (tid < QPC) {
            const int t = b * SN + qt * QPC + tid;
            float den = 0.f, num[8];
#pragma unroll
            for (int e = 0; e < 8; e++) num[e] = 0.f;
#pragma unroll
            for (int s = 0; s < KSPLIT; s++) {
                den += g_den[(size_t)t * KSPLIT + s];
                const float4* p = reinterpret_cast<const float4*>(
                    g_num + ((size_t)t * KSPLIT + s) * 8);
                float4 p0 = p[0], p1 = p[1];
                num[0] += p0.x; num[1] += p0.y; num[2] += p0.z; num[3] += p0.w;
                num[4] += p1.x; num[5] += p1.y; num[6] += p1.z; num[7] += p1.w;
            }
            float inv = 1.0f / den;
            float oo[8];
#pragma unroll
            for (int e = 0; e < 8; e++) oo[e] = num[e] * inv;
#pragma unroll
            for (int d = 0; d < 8; d++) {
                float y = __ldg(&bias[d]);
#pragma unroll
                for (int e = 0; e < 8; e++) y += oo[e] * __ldg(&W[d * 8 + e]);
                out[(size_t)t * 8 + d] = y;
            }
        }
        if (tid == 0) g_cnt[b * NQT + qt] = 0;   /* reset for next replay */
    }
}

extern "C" void kernel_launch(void* const* d_in, const int* in_sizes, int n_in,
                              void* d_out, int out_size) {
    const float* x     = (const float*)d_in[0];
    const float* phi_q = (const float*)d_in[1];
    const float* phi_k = (const float*)d_in[2];
    const float* phi_v = (const float*)d_in[3];
    const float* W     = (const float*)d_in[4];
    const float* bias  = (const float*)d_in[5];
    float* out = (float*)d_out;

    dim3 fgrid(NTOK / 128, 3);
    features_kernel<<<fgrid, 128>>>(x, phi_q, phi_k, phi_v);

    dim3 grid(NQT, KSPLIT, BN);
    attn_mma_kernel<<<grid, NTHR>>>(W, bias, out);
}

// round 13
// speedup vs baseline: 2.3667x; 1.0039x over previous
#include <cuda_runtime.h>
#include <cuda_bf16.h>
#include <cstdint>

#define BN 8
#define SN 2048
#define NTOK (BN*SN)
#define KSPLIT 4
#define SUBC 4                /* 128-key chunks per CTA */
#define NTHR 256              /* 8 warps; warp = 16 queries x 128 keys */
#define QPC 128               /* queries per CTA */
#define NQT (SN/QPC)          /* 16 query tiles */
#define LOG2E 1.4426950408889634f

/* Scratch (allocation-free rule: device globals), all in MMA-fragment order:
 * g_Qf: [wt = tok/16][lane][8]  a-reg order (tf32, *log2e)
 * g_Kf: [chunk = tok/128][tile = 16][lane][4]  b-frag words (tf32)
 * g_Vf: [chunk][s = 8][lane][2]  bf16x2 b-frag words for PV
 */
__device__ float    g_Qf[(size_t)NTOK * 16];
__device__ float    g_Kf[(size_t)NTOK * 16];
__device__ uint32_t g_Vf[(size_t)NTOK * 4];
__device__ float    g_den[(size_t)NTOK * KSPLIT];
__device__ float    g_num[(size_t)NTOK * KSPLIT * 8];
__device__ unsigned int g_cnt[BN * NQT];   /* zero-init; each run returns it to 0 */

__device__ __forceinline__ float ex2f(float x) {
    float y; asm("ex2.approx.ftz.f32 %0, %1;" : "=f"(y) : "f"(x)); return y;
}
__device__ __forceinline__ float tf32r(float x) {
    uint32_t u; asm("cvt.rna.tf32.f32 %0, %1;" : "=r"(u) : "f"(x));
    return __uint_as_float(u);
}
/* pack (lo,hi) -> bf16x2 word, lo in low half */
__device__ __forceinline__ uint32_t bf2(float lo, float hi) {
    uint32_t r; asm("cvt.rn.bf16x2.f32 %0, %1, %2;" : "=r"(r) : "f"(hi), "f"(lo)); return r;
}

/* tf32 m16n8k8: D += A*B  (fragment layouts verified in rounds 5/10) */
__device__ __forceinline__ void mma_tf32(float c[4], uint32_t a0, uint32_t a1,
                                         uint32_t a2, uint32_t a3,
                                         uint32_t b0, uint32_t b1) {
    asm("mma.sync.aligned.m16n8k8.row.col.f32.tf32.tf32.f32 "
        "{%0,%1,%2,%3}, {%4,%5,%6,%7}, {%8,%9}, {%0,%1,%2,%3};"
        : "+f"(c[0]), "+f"(c[1]), "+f"(c[2]), "+f"(c[3])
        : "r"(a0), "r"(a1), "r"(a2), "r"(a3), "r"(b0), "r"(b1));
}
/* bf16 m16n8k16: D += A*B */
__device__ __forceinline__ void mma_bf16(float c[4], uint32_t a0, uint32_t a1,
                                         uint32_t a2, uint32_t a3,
                                         uint32_t b0, uint32_t b1) {
    asm("mma.sync.aligned.m16n8k16.row.col.f32.bf16.bf16.f32 "
        "{%0,%1,%2,%3}, {%4,%5,%6,%7}, {%8,%9}, {%0,%1,%2,%3};"
        : "+f"(c[0]), "+f"(c[1]), "+f"(c[2]), "+f"(c[3])
        : "r"(a0), "r"(a1), "r"(a2), "r"(a3), "r"(b0), "r"(b1));
}

/* ---------------- Kernel 1: features -> fragment-ordered buffers ---------------- */
__device__ __forceinline__ void load_x8(const float* __restrict__ x, int tok, float xv[8]) {
    const float4* xp = reinterpret_cast<const float4*>(x + (size_t)tok * 8);
    float4 xa = xp[0], xb = xp[1];
    xv[0]=xa.x; xv[1]=xa.y; xv[2]=xa.z; xv[3]=xa.w;
    xv[4]=xb.x; xv[5]=xb.y; xv[6]=xb.z; xv[7]=xb.w;
}

__device__ __forceinline__ void qk_features16(const float xv[8], const float* __restrict__ ph,
                                              float F[16]) {
    float c[8];
#pragma unroll
    for (int u = 0; u < 8; u++) c[u] = __cosf(xv[u] + __ldg(&ph[u]));
    float q1 = c[0]*c[1], q2 = q1*c[2], q3 = q2*c[3];
    float q0 = c[1]*c[2]*c[3]*c[4]*c[5]*c[6]*c[7];
    float s0,s1,s2,s3,a0,a1,a2,a3;
    __sincosf(0.5f*q0, &s0, &a0);
    __sincosf(0.5f*q1, &s1, &a1);
    __sincosf(0.5f*q2, &s2, &a2);
    __sincosf(0.5f*q3, &s3, &a3);
    float t01[4] = {a0*a1, s0*a1, a0*s1, s0*s1};
    float t23[4] = {a2*a3, s2*a3, a2*s3, s2*s3};
#pragma unroll
    for (int m = 0; m < 16; m++) F[m] = t01[m & 3] * t23[m >> 2];
}

__global__ __launch_bounds__(128) void features_kernel(
        const float* __restrict__ x,
        const float* __restrict__ phi_q,
        const float* __restrict__ phi_k,
        const float* __restrict__ phi_v) {
    __shared__ float st[2048];   /* 8KB staging */
    const int tid = threadIdx.x;
    const int blk = blockIdx.x;              /* 128-token chunk index */
    const int t = blk * 128 + tid;
    const int kind = blockIdx.y;

    float xv[8];
    load_x8(x, t, xv);

    if (kind == 0) {
        /* Q a-reg order: [wt][lane = (gg&7)*4+t4][word = (f>>2)*2 + (gg>>3)] */
        float F[16];
        qk_features16(xv, phi_q, F);
        const int wt_l = tid >> 4, gg = tid & 15;
        float* base = st + wt_l * 256 + ((gg & 7) * 4) * 8 + (gg >> 3);
#pragma unroll
        for (int f = 0; f < 16; f++)
            base[(f & 3) * 8 + (f >> 2) * 2] = tf32r(F[f] * LOG2E);
        __syncthreads();
        float4* dst = reinterpret_cast<float4*>(g_Qf + (size_t)blk * 2048);
        const float4* s4 = reinterpret_cast<const float4*>(st);
#pragma unroll
        for (int i = 0; i < 4; i++) dst[tid + i * 128] = s4[tid + i * 128];
    } else if (kind == 1) {
        /* K b-frag order: [tile = kk>>3][lane = (kk&7)*4+t4][word = f>>2] */
        float F[16];
        qk_features16(xv, phi_k, F);
        const int j = tid >> 3, g = tid & 7;
        float* base = st + j * 128 + g * 16;
#pragma unroll
        for (int f = 0; f < 16; f++)
            base[(f & 3) * 4 + (f >> 2)] = tf32r(F[f]);
        __syncthreads();
        float4* dst = reinterpret_cast<float4*>(g_Kf + (size_t)blk * 2048);
        const float4* s4 = reinterpret_cast<const float4*>(st);
#pragma unroll
        for (int i = 0; i < 4; i++) dst[tid + i * 128] = s4[tid + i * 128];
    } else {
        /* V bf16 pair-words in PV b-frag order */
        float c[8];
#pragma unroll
        for (int u = 0; u < 8; u++) c[u] = __cosf(xv[u] + __ldg(&phi_v[u]));
        float v[8];
        v[1] = c[0]*c[1];
#pragma unroll
        for (int w = 2; w < 8; w++) v[w] = v[w-1]*c[w];
        v[0] = c[1]*c[2]*c[3]*c[4]*c[5]*c[6]*c[7];
        const int kq = tid;
        const int p = kq >> 1, h = kq & 1;
        const int s = p >> 3, rem = p & 7;
        const int w = rem >> 2, t4 = rem & 3;
        char* cb = reinterpret_cast<char*>(st) + s * 256;
#pragma unroll
        for (int cc = 0; cc < 8; cc++) {
            int word = (cc * 4 + t4) * 2 + w;
            *reinterpret_cast<__nv_bfloat16*>(cb + word * 4 + h * 2) = __float2bfloat16(v[cc]);
        }
        __syncthreads();
        if (tid < 128) {
            uint4* dst = reinterpret_cast<uint4*>(g_Vf + (size_t)blk * 512);
            dst[tid] = reinterpret_cast<const uint4*>(st)[tid];
        }
    }
}

/* ---------------- Kernel 2: mma.sync flash attention + fused finalize ----------------
 * Warp = 16 queries x 512 keys (4 chunks of 128 accumulated in C-frags).
 * s-iterations processed in PAIRS: 4 independent S chains, split PV/den
 * accumulators (A: even s, B: odd s) to halve accumulation-chain stalls.
 */
__global__ __launch_bounds__(NTHR) void attn_mma_kernel(
        const float* __restrict__ W,
        const float* __restrict__ bias,
        float* __restrict__ out) {
    __shared__ float    sKf[2048];   /* 8KB: 16 tiles x 32 lanes x 4 words */
    __shared__ uint32_t sVf[512];    /* 2KB: 8 s x 32 lanes x 2 words */
    __shared__ unsigned int s_old;

    const int b  = blockIdx.z;
    const int ks = blockIdx.y;
    const int qt = blockIdx.x;
    const int tid = threadIdx.x;
    const int w = tid >> 5, l = tid & 31;
    const int g = l >> 2, t4 = l & 3;

    /* Q a-regs (2 k-steps x 4 regs), loaded once per CTA */
    uint32_t qa[8];
    {
        const int wt = b * 128 + qt * 8 + w;
        const float4* qp = reinterpret_cast<const float4*>(
            g_Qf + (size_t)wt * 256 + (size_t)l * 8);
        float4 q0 = qp[0], q1 = qp[1];
        qa[0]=__float_as_uint(q0.x); qa[1]=__float_as_uint(q0.y);
        qa[2]=__float_as_uint(q0.z); qa[3]=__float_as_uint(q0.w);
        qa[4]=__float_as_uint(q1.x); qa[5]=__float_as_uint(q1.y);
        qa[6]=__float_as_uint(q1.z); qa[7]=__float_as_uint(q1.w);
    }

    /* ones-in-col-0 B-frag for the den MMA */
    const uint32_t ones = (g == 0) ? 0x3F803F80u : 0u;

    float oA[4]  = {0.f,0.f,0.f,0.f}, oB[4]  = {0.f,0.f,0.f,0.f};
    float o2A[4] = {0.f,0.f,0.f,0.f}, o2B[4] = {0.f,0.f,0.f,0.f};

    for (int c4 = 0; c4 < SUBC; c4++) {
        const int chunk = b * 16 + ks * SUBC + c4;
        __syncthreads();
        {
            const float4* kg = reinterpret_cast<const float4*>(g_Kf + (size_t)chunk * 2048);
            float4* sk4 = reinterpret_cast<float4*>(sKf);
#pragma unroll
            for (int i = 0; i < 2; i++) sk4[tid + i * NTHR] = kg[tid + i * NTHR];
            if (tid < 128) {
                const uint4* vg = reinterpret_cast<const uint4*>(g_Vf + (size_t)chunk * 512);
                reinterpret_cast<uint4*>(sVf)[tid] = vg[tid];
            }
        }
        __syncthreads();

#pragma unroll
        for (int sp = 0; sp < 4; sp++) {
            /* hoist all smem traffic for this PAIR of s-iterations */
            const float4 kb0 = *reinterpret_cast<const float4*>(&sKf[(4*sp)     * 128 + l * 4]);
            const float4 kb1 = *reinterpret_cast<const float4*>(&sKf[(4*sp + 1) * 128 + l * 4]);
            const float4 kb2 = *reinterpret_cast<const float4*>(&sKf[(4*sp + 2) * 128 + l * 4]);
            const float4 kb3 = *reinterpret_cast<const float4*>(&sKf[(4*sp + 3) * 128 + l * 4]);
            const uint2 vb0 = *reinterpret_cast<const uint2*>(&sVf[(2*sp)     * 64 + l * 2]);
            const uint2 vb1 = *reinterpret_cast<const uint2*>(&sVf[(2*sp + 1) * 64 + l * 2]);

            /* 4 independent S chains */
            float c0[4] = {0.f,0.f,0.f,0.f}, c1[4] = {0.f,0.f,0.f,0.f};
            float c2[4] = {0.f,0.f,0.f,0.f}, c3[4] = {0.f,0.f,0.f,0.f};
            mma_tf32(c0, qa[0],qa[1],qa[2],qa[3], __float_as_uint(kb0.x), __float_as_uint(kb0.y));
            mma_tf32(c1, qa[0],qa[1],qa[2],qa[3], __float_as_uint(kb1.x), __float_as_uint(kb1.y));
            mma_tf32(c2, qa[0],qa[1],qa[2],qa[3], __float_as_uint(kb2.x), __float_as_uint(kb2.y));
            mma_tf32(c3, qa[0],qa[1],qa[2],qa[3], __float_as_uint(kb3.x), __float_as_uint(kb3.y));
            mma_tf32(c0, qa[4],qa[5],qa[6],qa[7], __float_as_uint(kb0.z), __float_as_uint(kb0.w));
            mma_tf32(c1, qa[4],qa[5],qa[6],qa[7], __float_as_uint(kb1.z), __float_as_uint(kb1.w));
            mma_tf32(c2, qa[4],qa[5],qa[6],qa[7], __float_as_uint(kb2.z), __float_as_uint(kb2.w));
            mma_tf32(c3, qa[4],qa[5],qa[6],qa[7], __float_as_uint(kb3.z), __float_as_uint(kb3.w));

            /* exp (scores pre-scaled by log2e) */
            float e00 = ex2f(fabsf(c0[0])), e01 = ex2f(fabsf(c0[1]));
            float e02 = ex2f(fabsf(c0[2])), e03 = ex2f(fabsf(c0[3]));
            float e10 = ex2f(fabsf(c1[0])), e11 = ex2f(fabsf(c1[1]));
            float e12 = ex2f(fabsf(c1[2])), e13 = ex2f(fabsf(c1[3]));
            float e20 = ex2f(fabsf(c2[0])), e21 = ex2f(fabsf(c2[1]));
            float e22 = ex2f(fabsf(c2[2])), e23 = ex2f(fabsf(c2[3]));
            float e30 = ex2f(fabsf(c3[0])), e31 = ex2f(fabsf(c3[1]));
            float e32 = ex2f(fabsf(c3[2])), e33 = ex2f(fabsf(c3[3]));

            /* S C-frags -> PV A-frags (bf16) */
            uint32_t paA0 = bf2(e00, e01), paA1 = bf2(e02, e03);
            uint32_t paA2 = bf2(e10, e11), paA3 = bf2(e12, e13);
            uint32_t paB0 = bf2(e20, e21), paB1 = bf2(e22, e23);
            uint32_t paB2 = bf2(e30, e31), paB3 = bf2(e32, e33);

            /* split accumulators: A = even s, B = odd s */
            mma_bf16(oA,  paA0, paA1, paA2, paA3, vb0.x, vb0.y);
            mma_bf16(oB,  paB0, paB1, paB2, paB3, vb1.x, vb1.y);
            mma_bf16(o2A, paA0, paA1, paA2, paA3, ones, ones);
            mma_bf16(o2B, paB0, paB1, paB2, paB3, ones, ones);
        }
    }

    /* merge split accumulators */
    float o[4], o2r0, o2r2;
#pragma unroll
    for (int i = 0; i < 4; i++) o[i] = oA[i] + oB[i];
    o2r0 = o2A[0] + o2B[0];
    o2r2 = o2A[2] + o2B[2];

    /* write partials: o C-frag complete (comps 2t4,2t4+1 per row);
     * den valid at t4==0 (col 0): rows g and g+8. */
    const int tokA = b * SN + qt * QPC + w * 16 + g;
    const int tokB = tokA + 8;
    reinterpret_cast<float2*>(g_num + ((size_t)tokA * KSPLIT + ks) * 8)[t4] =
        make_float2(o[0], o[1]);
    reinterpret_cast<float2*>(g_num + ((size_t)tokB * KSPLIT + ks) * 8)[t4] =
        make_float2(o[2], o[3]);
    if (t4 == 0) {
        g_den[(size_t)tokA * KSPLIT + ks] = o2r0;
        g_den[(size_t)tokB * KSPLIT + ks] = o2r2;
    }

    /* ---- fused finalize: last-arriving CTA per (b,qt) ---- */
    __threadfence();
    if (tid == 0) s_old = atomicAdd(&g_cnt[b * NQT + qt], 1u);
    __syncthreads();

    if (s_old == KSPLIT - 1) {
        if (tid < QPC) {
            const int t = b * SN + qt * QPC + tid;
            float den = 0.f, num[8];
#pragma unroll
            for (int e = 0; e < 8; e++) num[e] = 0.f;
#pragma unroll
            for (int s = 0; s < KSPLIT; s++) {
                den += g_den[(size_t)t * KSPLIT + s];
                const float4* p = reinterpret_cast<const float4*>(
                    g_num + ((size_t)t * KSPLIT + s) * 8);
                float4 p0 = p[0], p1 = p[1];
                num[0] += p0.x; num[1] += p0.y; num[2] += p0.z; num[3] += p0.w;
                num[4] += p1.x; num[5] += p1.y; num[6] += p1.z; num[7] += p1.w;
            }
            float inv = 1.0f / den;
            float oo[8];
#pragma unroll
            for (int e = 0; e < 8; e++) oo[e] = num[e] * inv;
#pragma unroll
            for (int d = 0; d < 8; d++) {
                float y = __ldg(&bias[d]);
#pragma unroll
                for (int e = 0; e < 8; e++) y += oo[e] * __ldg(&W[d * 8 + e]);
                out[(size_t)t * 8 + d] = y;
            }
        }
        if (tid == 0) g_cnt[b * NQT + qt] = 0;   /* reset for next replay */
    }
}

extern "C" void kernel_launch(void* const* d_in, const int* in_sizes, int n_in,
                              void* d_out, int out_size) {
    const float* x     = (const float*)d_in[0];
    const float* phi_q = (const float*)d_in[1];
    const float* phi_k = (const float*)d_in[2];
    const float* phi_v = (const float*)d_in[3];
    const float* W     = (const float*)d_in[4];
    const float* bias  = (const float*)d_in[5];
    float* out = (float*)d_out;

    dim3 fgrid(NTOK / 128, 3);
    features_kernel<<<fgrid, 128>>>(x, phi_q, phi_k, phi_v);

    dim3 grid(NQT, KSPLIT, BN);
    attn_mma_kernel<<<grid, NTHR>>>(W, bias, out);
}